// round 11
// baseline (speedup 1.0000x reference)
#include <cuda_runtime.h>
#include <math.h>
#include <stdint.h>

// VectorQuantizer: N=131072 rows (dim 64) vs 512 codes.
// Two-pass: packed fma.rn.f32x2 screen (ranks by c2-2*mm, x2 dropped as a
// per-row constant) + exact reference-order fp32 rescore for rows whose
// top-2 screen gap <= EPS. Persistent 148 blocks x 512 threads (4 warps/SMSP).
// Out (fp32): [0,8388608) quantized_st; [8388608,8519680) codes;
//             then commitment*0.25, codebook_loss, perplexity.
#define K_CODES 512
#define DIMV 64
#define NROWS 131072
#define TPB 512
#define NBLK 148
#define ROWS_PER_BLK ((NROWS + NBLK - 1) / NBLK)   // 886
#define EPS 1.2e-4f

typedef unsigned long long u64;
typedef unsigned int u32;

__device__ double g_sqsum;
__device__ int g_counts[K_CODES];

__device__ __forceinline__ float lof(u64 p) { return __int_as_float((int)(u32)p); }
__device__ __forceinline__ float hif(u64 p) { return __int_as_float((int)(u32)(p >> 32)); }
__device__ __forceinline__ void ffma2(u64& d, u64 a, u64 b) {
    asm("fma.rn.f32x2 %0, %1, %2, %0;" : "+l"(d) : "l"(a), "l"(b));
}

__global__ void vq_init_kernel() {
    int t = blockIdx.x * blockDim.x + threadIdx.x;
    if (t == 0) g_sqsum = 0.0;
    if (t < K_CODES) g_counts[t] = 0;
}

// Exact reference-order score: sequential fma chain d=0..63 against smem
// codebook, then round(round(x2 - 2*mm) + c2). xl is a rare-path local buffer.
__device__ __forceinline__ float exact_score_sm(const float* __restrict__ scb,
                                                int k, float c2,
                                                const float* xl, float x2) {
    const float* c = scb + k * DIMV;
    float m = 0.f;
    #pragma unroll
    for (int d = 0; d < DIMV; ++d) m = __fmaf_rn(xl[d], c[d], m);
    return __fadd_rn(__fadd_rn(x2, -2.f * m), c2);
}

__global__ __launch_bounds__(TPB, 1)
void vq_main_kernel(const float* __restrict__ latents,
                    const float* __restrict__ codebook,
                    float* __restrict__ out) {
    extern __shared__ float smem[];
    float* scb   = smem;                        // 512*64 floats, natural layout
    float* sc2   = smem + K_CODES * DIMV;       // 512
    int*   shist = (int*)(sc2 + K_CODES);       // 512
    float* sred  = (float*)(shist + K_CODES);   // TPB

    const int tid = threadIdx.x;

    const float4* cb4 = (const float4*)codebook;
    float4* scb4 = (float4*)scb;
    for (int i = tid; i < K_CODES * DIMV / 4; i += TPB)
        scb4[i] = cb4[i];
    for (int k = tid; k < K_CODES; k += TPB) shist[k] = 0;
    __syncthreads();
    // c2 in reference rounding order.
    for (int k = tid; k < K_CODES; k += TPB) {
        float s = 0.f;
        const float* c = scb + k * DIMV;
        #pragma unroll
        for (int d = 0; d < DIMV; ++d) s = __fadd_rn(s, __fmul_rn(c[d], c[d]));
        sc2[k] = s;
    }
    __syncthreads();

    const int row0 = blockIdx.x * ROWS_PER_BLK;
    const int rowEnd = min(row0 + ROWS_PER_BLK, NROWS);
    float sqAcc = 0.f;

    for (int row = row0 + tid; row < rowEnd; row += TPB) {
        // Latent row as 32 packed fp32-pairs (fp32 pair layout == f32x2 lanes).
        u64 xp[32];
        const ulonglong2* lp = (const ulonglong2*)(latents + (size_t)row * DIMV);
        #pragma unroll
        for (int i = 0; i < 16; ++i) {
            ulonglong2 t = lp[i];
            xp[2 * i] = t.x;
            xp[2 * i + 1] = t.y;
        }

        // ---- screen: rank by fma(-2, mm_approx, c2); track 3 smallest ----
        float s0 = 3.4e38f, s1 = 3.4e38f, s2v = 3.4e38f;
        int k0 = 0, k1 = 0;
        for (int kb = 0; kb < K_CODES; kb += 8) {
            u64 acc[8];
            #pragma unroll
            for (int j = 0; j < 8; ++j) acc[j] = 0ull;
            #pragma unroll
            for (int i = 0; i < 16; ++i) {
                const u64 xa = xp[2 * i], xb = xp[2 * i + 1];
                #pragma unroll
                for (int j = 0; j < 8; ++j) {
                    ulonglong2 c = ((const ulonglong2*)(scb + (kb + j) * DIMV))[i];
                    ffma2(acc[j], xa, c.x);
                    ffma2(acc[j], xb, c.y);
                }
            }
            #pragma unroll
            for (int j = 0; j < 8; ++j) {
                float mm = __fadd_rn(lof(acc[j]), hif(acc[j]));
                float s = __fmaf_rn(-2.f, mm, sc2[kb + j]);
                if (s < s2v) {
                    if (s < s1) {
                        if (s < s0) { s2v = s1; s1 = s0; k1 = k0; s0 = s; k0 = kb + j; }
                        else        { s2v = s1; s1 = s;  k1 = kb + j; }
                    } else          { s2v = s; }
                }
            }
        }

        // ---- resolve: exact reference-order rescore for ambiguous rows ----
        int bestk = k0;
        if (s1 - s0 <= EPS) {
            // rare path (~2.5% rows): rebuild x in a scratch buffer
            float xl[DIMV];
            const float* xg = latents + (size_t)row * DIMV;
            #pragma unroll
            for (int d = 0; d < DIMV; ++d) xl[d] = xg[d];
            float x2 = 0.f;
            #pragma unroll
            for (int d = 0; d < DIMV; ++d) x2 = __fadd_rn(x2, __fmul_rn(xl[d], xl[d]));
            if (s2v - s0 <= EPS) {
                // very rare: full exact first-min scan
                float best = 3.4e38f; bestk = 0;
                for (int k = 0; k < K_CODES; ++k) {
                    float e = exact_score_sm(scb, k, sc2[k], xl, x2);
                    if (e < best) { best = e; bestk = k; }
                }
            } else {
                float e0 = exact_score_sm(scb, k0, sc2[k0], xl, x2);
                float e1 = exact_score_sm(scb, k1, sc2[k1], xl, x2);
                // first-min: on exact tie pick lower index
                bestk = k0;
                if (e1 < e0 || (e1 == e0 && k1 < k0)) bestk = k1;
            }
        }

        // ---- epilogue: ST output (reference roundings) + loss partial ----
        float* qout = out + (size_t)row * DIMV;
        const float4* cq = (const float4*)(scb + bestk * DIMV);
        float rowsq = 0.f;
        #pragma unroll
        for (int i = 0; i < 16; ++i) {
            float4 q = cq[i];
            float lx = lof(xp[2 * i]),     ly = hif(xp[2 * i]);
            float lz = lof(xp[2 * i + 1]), lw = hif(xp[2 * i + 1]);
            float4 o;
            o.x = __fadd_rn(lx, __fsub_rn(q.x, lx));
            o.y = __fadd_rn(ly, __fsub_rn(q.y, ly));
            o.z = __fadd_rn(lz, __fsub_rn(q.z, lz));
            o.w = __fadd_rn(lw, __fsub_rn(q.w, lw));
            ((float4*)qout)[i] = o;
            float dx = lx - q.x, dy = ly - q.y, dz = lz - q.z, dw = lw - q.w;
            rowsq = fmaf(dx, dx, rowsq);
            rowsq = fmaf(dy, dy, rowsq);
            rowsq = fmaf(dz, dz, rowsq);
            rowsq = fmaf(dw, dw, rowsq);
        }
        out[(size_t)NROWS * DIMV + row] = (float)bestk;
        atomicAdd(&shist[bestk], 1);
        sqAcc += rowsq;
    }

    // ---- reductions ----
    sred[tid] = sqAcc;
    __syncthreads();
    for (int s = TPB / 2; s > 0; s >>= 1) {
        if (tid < s) sred[tid] += sred[tid + s];
        __syncthreads();
    }
    if (tid == 0) atomicAdd(&g_sqsum, (double)sred[0]);
    for (int k = tid; k < K_CODES; k += TPB) {
        int c = shist[k];
        if (c) atomicAdd(&g_counts[k], c);
    }
}

__global__ void vq_finalize_kernel(float* __restrict__ out) {
    __shared__ float red[K_CODES];
    int t = threadIdx.x;
    float p = (float)g_counts[t] / (float)NROWS;
    red[t] = -p * logf(p + 1e-10f);
    __syncthreads();
    for (int s = K_CODES / 2; s > 0; s >>= 1) {
        if (t < s) red[t] += red[t + s];
        __syncthreads();
    }
    if (t == 0) {
        float perp = expf(red[0]);
        float msd = (float)(g_sqsum / (double)((size_t)NROWS * DIMV));
        size_t base = (size_t)NROWS * DIMV + NROWS;
        out[base + 0] = msd * 0.25f;   // commitment * COMMITMENT_COST
        out[base + 1] = msd;           // codebook loss
        out[base + 2] = perp;          // perplexity
    }
}

extern "C" void kernel_launch(void* const* d_in, const int* in_sizes, int n_in,
                              void* d_out, int out_size) {
    (void)in_sizes; (void)n_in; (void)out_size;
    const float* latents  = (const float*)d_in[0];
    const float* codebook = (const float*)d_in[1];
    float* out = (float*)d_out;

    const int smem_bytes = (K_CODES * DIMV) * 4 + K_CODES * 4 + K_CODES * 4 + TPB * 4;
    cudaFuncSetAttribute(vq_main_kernel,
                         cudaFuncAttributeMaxDynamicSharedMemorySize, smem_bytes);

    vq_init_kernel<<<2, 256>>>();
    vq_main_kernel<<<NBLK, TPB, smem_bytes>>>(latents, codebook, out);
    vq_finalize_kernel<<<1, K_CODES>>>(out);
}